// round 10
// baseline (speedup 1.0000x reference)
#include <cuda_runtime.h>
#include <cuda_bf16.h>
#include <math.h>

#define NN 50000
#define NE 500000
#define ET (NE + NN)   /* edges + self loops = 550000 */
#define DIN 128
#define DD 256
#define HH 8
#define CC 32

// ---------------- scratch (static device globals; no allocation) ----------------
__device__ float g_h1[(size_t)NN * DD];   // layer1 GEMM out  [N,256]
__device__ float g_h2[(size_t)NN * DD];   // layer2 GEMM out  [N,256]
__device__ float g_es1[NN * HH];
__device__ float g_ed1[NN * HH];
__device__ float g_es2[NN];
__device__ float g_ed2[NN];
__device__ int   g_cnt[NN];
__device__ int   g_off[NN + 1];
__device__ int   g_cur[NN];
__device__ int   g_srcl[ET];
#define SCB 512
#define NBL ((NN + SCB - 1) / SCB)   /* 98 */
__device__ int   g_bsum[NBL];
// pre-split bf16 operands (padded +128 rows so tail-tile reads stay in bounds)
__device__ __nv_bfloat16 g_a1h[(size_t)(NN + 128) * DIN];
__device__ __nv_bfloat16 g_a1l[(size_t)(NN + 128) * DIN];
__device__ __nv_bfloat16 g_acth[(size_t)(NN + 128) * DD];
__device__ __nv_bfloat16 g_actl[(size_t)(NN + 128) * DD];
// transposed + bf16-split weights: Bt[n][k] = W[k][n]
__device__ __nv_bfloat16 g_bt1h[256 * 128];
__device__ __nv_bfloat16 g_bt1l[256 * 128];
__device__ __nv_bfloat16 g_bt2h[256 * 256];
__device__ __nv_bfloat16 g_bt2l[256 * 256];

// ---------------- helpers ----------------
__device__ __forceinline__ void cvt2(float a, float b, unsigned& hi, unsigned& lo) {
    __nv_bfloat16 ah = __float2bfloat16_rn(a), bh = __float2bfloat16_rn(b);
    float al = a - __bfloat162float(ah), bl = b - __bfloat162float(bh);
    __nv_bfloat16 alh = __float2bfloat16_rn(al), blh = __float2bfloat16_rn(bl);
    unsigned short au = *(unsigned short*)&ah, bu = *(unsigned short*)&bh;
    unsigned short alu = *(unsigned short*)&alh, blu = *(unsigned short*)&blh;
    hi = (unsigned)au | ((unsigned)bu << 16);
    lo = (unsigned)alu | ((unsigned)blu << 16);
}

__device__ __forceinline__ void mma16816(float* c, const unsigned* a, unsigned b0, unsigned b1) {
    asm volatile(
        "mma.sync.aligned.m16n8k16.row.col.f32.bf16.bf16.f32 "
        "{%0,%1,%2,%3}, {%4,%5,%6,%7}, {%8,%9}, {%0,%1,%2,%3};"
        : "+f"(c[0]), "+f"(c[1]), "+f"(c[2]), "+f"(c[3])
        : "r"(a[0]), "r"(a[1]), "r"(a[2]), "r"(a[3]), "r"(b0), "r"(b1));
}

__device__ __forceinline__ void ldsm_x4(unsigned* r, unsigned addr) {
    asm volatile("ldmatrix.sync.aligned.m8n8.x4.shared.b16 {%0,%1,%2,%3}, [%4];"
                 : "=r"(r[0]), "=r"(r[1]), "=r"(r[2]), "=r"(r[3]) : "r"(addr));
}

__device__ __forceinline__ float lrelu(float e) { return e > 0.f ? e : 0.2f * e; }

// ---------------- CSR build ----------------
__global__ void k_zero() {
    int i = blockIdx.x * blockDim.x + threadIdx.x;
    if (i < NN) { g_cnt[i] = 0; g_es2[i] = 0.f; g_ed2[i] = 0.f; }
}

__global__ void k_count(const int* __restrict__ ei) {
    int t = blockIdx.x * blockDim.x + threadIdx.x;
    if (t >= ET) return;
    int dst = (t < NE) ? ei[NE + t] : (t - NE);
    atomicAdd(&g_cnt[dst], 1);
}

__global__ void k_scan1() {
    __shared__ int wsum[16];
    int t = threadIdx.x;
    int i = blockIdx.x * SCB + t;
    int v = (i < NN) ? g_cnt[i] : 0;
#pragma unroll
    for (int o = 16; o; o >>= 1) v += __shfl_xor_sync(0xFFFFFFFFu, v, o);
    if ((t & 31) == 0) wsum[t >> 5] = v;
    __syncthreads();
    if (t < 16) {
        int s = wsum[t];
#pragma unroll
        for (int o = 8; o; o >>= 1) s += __shfl_xor_sync(0xFFFFu, s, o);
        if (t == 0) g_bsum[blockIdx.x] = s;
    }
}

__global__ void k_scan2() {
    __shared__ int s[128];
    int t = threadIdx.x;
    int v = (t < NBL) ? g_bsum[t] : 0;
    s[t] = v;
    __syncthreads();
#pragma unroll
    for (int d = 1; d < 128; d <<= 1) {
        int u = (t >= d) ? s[t - d] : 0;
        __syncthreads();
        s[t] += u;
        __syncthreads();
    }
    if (t < NBL) g_bsum[t] = s[t] - v;   // exclusive
    if (t == 0) g_off[NN] = ET;
}

__global__ void k_scan3() {
    __shared__ int s[SCB];
    int t = threadIdx.x;
    int i = blockIdx.x * SCB + t;
    int v = (i < NN) ? g_cnt[i] : 0;
    s[t] = v;
    __syncthreads();
#pragma unroll
    for (int d = 1; d < SCB; d <<= 1) {
        int u = (t >= d) ? s[t - d] : 0;
        __syncthreads();
        s[t] += u;
        __syncthreads();
    }
    if (i < NN) {
        int e = s[t] - v + g_bsum[blockIdx.x];
        g_off[i] = e;
        g_cur[i] = e;
    }
}

__global__ void k_scatter(const int* __restrict__ ei) {
    int t = blockIdx.x * blockDim.x + threadIdx.x;
    if (t >= ET) return;
    int src, dst;
    if (t < NE) { src = ei[t]; dst = ei[NE + t]; }
    else        { src = t - NE; dst = t - NE; }
    int pos = atomicAdd(&g_cur[dst], 1);
    g_srcl[pos] = src;
}

// ---------------- operand prep: bf16 split of x and W ----------------
__global__ void k_prepA(const float* __restrict__ x) {
    int t = blockIdx.x * blockDim.x + threadIdx.x;   // one thread per 4 floats
    if (t >= NN * DIN / 4) return;
    float4 v = ((const float4*)x)[t];
    unsigned h0, l0, h1, l1;
    cvt2(v.x, v.y, h0, l0);
    cvt2(v.z, v.w, h1, l1);
    ((uint2*)g_a1h)[t] = make_uint2(h0, h1);
    ((uint2*)g_a1l)[t] = make_uint2(l0, l1);
}

__global__ void k_prepB(const float* __restrict__ W1, const float* __restrict__ W2) {
    int t = blockIdx.x * blockDim.x + threadIdx.x;
    if (t < 256 * 128) {
        int n = t >> 7, k = t & 127;
        float v = W1[k * 256 + n];
        __nv_bfloat16 h = __float2bfloat16_rn(v);
        g_bt1h[n * 128 + k] = h;
        g_bt1l[n * 128 + k] = __float2bfloat16_rn(v - __bfloat162float(h));
    }
    int t2 = t - 256 * 128;
    if (t2 >= 0 && t2 < 256 * 256) {
        int n = t2 >> 8, k = t2 & 255;
        float v = W2[k * 256 + n];
        __nv_bfloat16 h = __float2bfloat16_rn(v);
        g_bt2h[n * 256 + k] = h;
        g_bt2l[n * 256 + k] = __float2bfloat16_rn(v - __bfloat162float(h));
    }
}

// ---------------- HMMA GEMM, double-buffered, ldmatrix frags, pure-copy staging ------
#define SROW 40
#define BUFSZ 40960
#define PLANE 10240

template <int L>
__global__ __launch_bounds__(256)
void k_gemm_mma(const float* __restrict__ asrc, const float* __restrict__ adst) {
    constexpr int KD = (L == 1) ? 128 : 256;
    constexpr int NCH = KD / 32;
    float* Cc = (L == 1) ? g_h1 : g_h2;
    const __nv_bfloat16* Ah = (L == 1) ? g_a1h : g_acth;
    const __nv_bfloat16* Al = (L == 1) ? g_a1l : g_actl;
    const __nv_bfloat16* Bh = (L == 1) ? g_bt1h : g_bt2h;
    const __nv_bfloat16* Bl = (L == 1) ? g_bt1l : g_bt2l;

    extern __shared__ char smem[];
    unsigned sbase = (unsigned)__cvta_generic_to_shared(smem);

    int tid = threadIdx.x, wid = tid >> 5, lane = tid & 31;
    int warpM = wid >> 1, warpN = wid & 1;       // 4 x 2 warp grid
    int row0 = blockIdx.y * 128, col0 = blockIdx.x * 128;

    // unified staging geometry: seg = tid*8+it covers A(1024 segs) then B(1024 segs)
    // each seg = one 16B copy: plane buf (hi/lo), row r, col-group sg
    const __nv_bfloat16* srcbase[4];
    srcbase[0] = Ah + (size_t)row0 * KD;
    srcbase[1] = Al + (size_t)row0 * KD;
    srcbase[2] = Bh + (size_t)col0 * KD;
    srcbase[3] = Bl + (size_t)col0 * KD;

    // ldmatrix lane geometry
    int g = lane >> 3, ri = lane & 7;
    int a_row = warpM * 32 + ((g & 1) ? 8 : 0) + ri;       // + mt*16 later
    int a_colx = (g & 2) ? 8 : 0;                          // + kt*16
    int b_row = warpN * 64 + ((g & 2) ? 8 : 0) + ri;       // + ntp*16
    int b_colx = (g & 1) ? 8 : 0;                          // + kt*16

    float acc[2][8][4];
#pragma unroll
    for (int mt = 0; mt < 2; mt++)
#pragma unroll
        for (int nt = 0; nt < 8; nt++)
#pragma unroll
            for (int q = 0; q < 4; q++) acc[mt][nt][q] = 0.f;

    uint4 pf[8];

    // per-seg constants
    int segP[8], segR[8], segS[8];
#pragma unroll
    for (int it = 0; it < 8; it++) {
        int seg = tid * 8 + it;          // 0..2047
        segP[it] = seg >> 9;             // 0:Ah 1:Al 2:Bh 3:Bl
        int s = seg & 511;
        segR[it] = s >> 2;               // row 0..127
        segS[it] = s & 3;                // 8-elem col group
    }

    // ---- load + stage chunk 0 into buffer 0 ----
#pragma unroll
    for (int it = 0; it < 8; it++)
        pf[it] = *(const uint4*)(srcbase[segP[it]] + (size_t)segR[it] * KD + segS[it] * 8);
    {
        char* base = smem;
#pragma unroll
        for (int it = 0; it < 8; it++) {
            int p = segP[it];
            int off = ((p >> 1) ? 20480 : 0) + (p & 1) * PLANE;
            *(uint4*)(base + off + segR[it] * 80 + segS[it] * 16) = pf[it];
        }
    }
    __syncthreads();

    for (int ch = 0; ch < NCH; ch++) {
        // ---- prefetch next chunk's globals ----
        if (ch + 1 < NCH) {
#pragma unroll
            for (int it = 0; it < 8; it++)
                pf[it] = *(const uint4*)(srcbase[segP[it]] + (size_t)segR[it] * KD +
                                         (ch + 1) * 32 + segS[it] * 8);
        }
        // ---- MMA on current buffer (ldmatrix fragment loads) ----
        {
            unsigned aHb = sbase + (unsigned)((ch & 1) * BUFSZ);
            unsigned aLb = aHb + PLANE;
            unsigned bHb = aHb + 20480;
            unsigned bLb = aHb + 30720;
#pragma unroll
            for (int kt = 0; kt < 2; kt++) {
                int acol = kt * 16 + a_colx;
                int bcol = kt * 16 + b_colx;
                unsigned aH[2][4], aL[2][4];
#pragma unroll
                for (int mt = 0; mt < 2; mt++) {
                    unsigned off = (unsigned)((a_row + mt * 16) * SROW + acol) * 2u;
                    ldsm_x4(aH[mt], aHb + off);
                    ldsm_x4(aL[mt], aLb + off);
                }
#pragma unroll
                for (int ntp = 0; ntp < 4; ntp++) {
                    unsigned off = (unsigned)((b_row + ntp * 16) * SROW + bcol) * 2u;
                    unsigned bH4[4], bL4[4];
                    ldsm_x4(bH4, bHb + off);
                    ldsm_x4(bL4, bLb + off);
#pragma unroll
                    for (int h = 0; h < 2; h++) {
                        int nt = ntp * 2 + h;
                        unsigned bH0 = bH4[h * 2], bH1 = bH4[h * 2 + 1];
                        unsigned bL0 = bL4[h * 2], bL1 = bL4[h * 2 + 1];
                        mma16816(acc[0][nt], aH[0], bH0, bH1);
                        mma16816(acc[1][nt], aH[1], bH0, bH1);
                        mma16816(acc[0][nt], aH[0], bL0, bL1);
                        mma16816(acc[1][nt], aH[1], bL0, bL1);
                        mma16816(acc[0][nt], aL[0], bH0, bH1);
                        mma16816(acc[1][nt], aL[1], bH0, bH1);
                    }
                }
            }
        }
        // ---- stage next chunk into the other buffer ----
        if (ch + 1 < NCH) {
            char* base = smem + ((ch + 1) & 1) * BUFSZ;
#pragma unroll
            for (int it = 0; it < 8; it++) {
                int p = segP[it];
                int off = ((p >> 1) ? 20480 : 0) + (p & 1) * PLANE;
                *(uint4*)(base + off + segR[it] * 80 + segS[it] * 16) = pf[it];
            }
        }
        __syncthreads();
    }

    // ---- epilogue: store C ----
#pragma unroll
    for (int mt = 0; mt < 2; mt++) {
        int r_lo = row0 + warpM * 32 + mt * 16 + (lane >> 2);
        int cc = col0 + warpN * 64 + (lane & 3) * 2;
#pragma unroll
        for (int nt = 0; nt < 8; nt++) {
            if (r_lo < NN)
                *(float2*)(Cc + (size_t)r_lo * DD + cc + nt * 8) =
                    make_float2(acc[mt][nt][0], acc[mt][nt][1]);
            if (r_lo + 8 < NN)
                *(float2*)(Cc + (size_t)(r_lo + 8) * DD + cc + nt * 8) =
                    make_float2(acc[mt][nt][2], acc[mt][nt][3]);
        }
    }

    // ---- fused attention coefficient dots ----
    if (L == 1) {
        float pes[2][2][2], ped[2][2][2];
#pragma unroll
        for (int a0 = 0; a0 < 2; a0++)
#pragma unroll
            for (int a1 = 0; a1 < 2; a1++)
#pragma unroll
                for (int a2 = 0; a2 < 2; a2++) { pes[a0][a1][a2] = 0.f; ped[a0][a1][a2] = 0.f; }
#pragma unroll
        for (int nt = 0; nt < 8; nt++) {
            int colg = col0 + warpN * 64 + nt * 8 + (lane & 3) * 2;
            float a0s = __ldg(asrc + colg), a1s = __ldg(asrc + colg + 1);
            float a0d = __ldg(adst + colg), a1d = __ldg(adst + colg + 1);
            int hb = nt >> 2;
#pragma unroll
            for (int mt = 0; mt < 2; mt++) {
                pes[mt][0][hb] += acc[mt][nt][0] * a0s + acc[mt][nt][1] * a1s;
                pes[mt][1][hb] += acc[mt][nt][2] * a0s + acc[mt][nt][3] * a1s;
                ped[mt][0][hb] += acc[mt][nt][0] * a0d + acc[mt][nt][1] * a1d;
                ped[mt][1][hb] += acc[mt][nt][2] * a0d + acc[mt][nt][3] * a1d;
            }
        }
#pragma unroll
        for (int a0 = 0; a0 < 2; a0++)
#pragma unroll
            for (int a1 = 0; a1 < 2; a1++)
#pragma unroll
                for (int a2 = 0; a2 < 2; a2++) {
                    pes[a0][a1][a2] += __shfl_xor_sync(0xFFFFFFFFu, pes[a0][a1][a2], 1);
                    pes[a0][a1][a2] += __shfl_xor_sync(0xFFFFFFFFu, pes[a0][a1][a2], 2);
                    ped[a0][a1][a2] += __shfl_xor_sync(0xFFFFFFFFu, ped[a0][a1][a2], 1);
                    ped[a0][a1][a2] += __shfl_xor_sync(0xFFFFFFFFu, ped[a0][a1][a2], 2);
                }
        if ((lane & 3) == 0) {
#pragma unroll
            for (int mt = 0; mt < 2; mt++)
#pragma unroll
                for (int rs = 0; rs < 2; rs++) {
                    int node = row0 + warpM * 32 + mt * 16 + (lane >> 2) + rs * 8;
                    if (node < NN) {
#pragma unroll
                        for (int hb = 0; hb < 2; hb++) {
                            int head = blockIdx.x * 4 + warpN * 2 + hb;
                            g_es1[node * 8 + head] = pes[mt][rs][hb];
                            g_ed1[node * 8 + head] = ped[mt][rs][hb];
                        }
                    }
                }
        }
    } else {
        float pes[2][2], ped[2][2];
#pragma unroll
        for (int a0 = 0; a0 < 2; a0++)
#pragma unroll
            for (int a1 = 0; a1 < 2; a1++) { pes[a0][a1] = 0.f; ped[a0][a1] = 0.f; }
#pragma unroll
        for (int nt = 0; nt < 8; nt++) {
            int colg = col0 + warpN * 64 + nt * 8 + (lane & 3) * 2;
            float a0s = __ldg(asrc + colg), a1s = __ldg(asrc + colg + 1);
            float a0d = __ldg(adst + colg), a1d = __ldg(adst + colg + 1);
#pragma unroll
            for (int mt = 0; mt < 2; mt++) {
                pes[mt][0] += acc[mt][nt][0] * a0s + acc[mt][nt][1] * a1s;
                pes[mt][1] += acc[mt][nt][2] * a0s + acc[mt][nt][3] * a1s;
                ped[mt][0] += acc[mt][nt][0] * a0d + acc[mt][nt][1] * a1d;
                ped[mt][1] += acc[mt][nt][2] * a0d + acc[mt][nt][3] * a1d;
            }
        }
#pragma unroll
        for (int a0 = 0; a0 < 2; a0++)
#pragma unroll
            for (int a1 = 0; a1 < 2; a1++) {
                pes[a0][a1] += __shfl_xor_sync(0xFFFFFFFFu, pes[a0][a1], 1);
                pes[a0][a1] += __shfl_xor_sync(0xFFFFFFFFu, pes[a0][a1], 2);
                ped[a0][a1] += __shfl_xor_sync(0xFFFFFFFFu, ped[a0][a1], 1);
                ped[a0][a1] += __shfl_xor_sync(0xFFFFFFFFu, ped[a0][a1], 2);
            }
        if ((lane & 3) == 0) {
#pragma unroll
            for (int mt = 0; mt < 2; mt++)
#pragma unroll
                for (int rs = 0; rs < 2; rs++) {
                    int node = row0 + warpM * 32 + mt * 16 + (lane >> 2) + rs * 8;
                    if (node < NN) {
                        atomicAdd(&g_es2[node], pes[mt][rs]);
                        atomicAdd(&g_ed2[node], ped[mt][rs]);
                    }
                }
        }
    }
}

// ---------------- GAT layer 1: warp per dst node; lane owns 8 cols of one head -------
// exp in-place; output stored directly as split bf16 for GEMM2
__global__ void k_gat1(const float* __restrict__ b1) {
    int n = (blockIdx.x * blockDim.x + threadIdx.x) >> 5;
    int lane = threadIdx.x & 31;
    if (n >= NN) return;
    int beg = g_off[n], end = g_off[n + 1];
    int col = lane * 8;           // cols [col, col+8) all in head lane>>2
    int head = lane >> 2;

    float ed_h = g_ed1[n * HH + head];

    float s = 0.f;
    float acc[8];
#pragma unroll
    for (int q = 0; q < 8; q++) acc[q] = 0.f;

#pragma unroll 8
    for (int i = beg; i < end; i++) {
        int sc = g_srcl[i];
        float w = __expf(lrelu(g_es1[sc * HH + head] + ed_h));
        const float* hrow = g_h1 + (size_t)sc * DD + col;
        float4 h0 = *(const float4*)(hrow);
        float4 h1 = *(const float4*)(hrow + 4);
        s += w;
        acc[0] = fmaf(w, h0.x, acc[0]);
        acc[1] = fmaf(w, h0.y, acc[1]);
        acc[2] = fmaf(w, h0.z, acc[2]);
        acc[3] = fmaf(w, h0.w, acc[3]);
        acc[4] = fmaf(w, h1.x, acc[4]);
        acc[5] = fmaf(w, h1.y, acc[5]);
        acc[6] = fmaf(w, h1.z, acc[6]);
        acc[7] = fmaf(w, h1.w, acc[7]);
    }
    float inv = 1.f / (s + 1e-16f);
    float res[8];
#pragma unroll
    for (int q = 0; q < 8; q++) {
        float v = acc[q] * inv + b1[col + q];
        res[q] = v > 0.f ? v : expm1f(v);  // ELU
    }
    unsigned hh[4], ll[4];
    cvt2(res[0], res[1], hh[0], ll[0]);
    cvt2(res[2], res[3], hh[1], ll[1]);
    cvt2(res[4], res[5], hh[2], ll[2]);
    cvt2(res[6], res[7], hh[3], ll[3]);
    *(uint4*)(g_acth + (size_t)n * DD + col) = make_uint4(hh[0], hh[1], hh[2], hh[3]);
    *(uint4*)(g_actl + (size_t)n * DD + col) = make_uint4(ll[0], ll[1], ll[2], ll[3]);
}

// ---------------- GAT layer 2 (H=1, C=256): warp per dst node, lane owns 8 cols ------
__global__ void k_gat2(const float* __restrict__ b2, float* __restrict__ out) {
    int n = (blockIdx.x * blockDim.x + threadIdx.x) >> 5;
    int lane = threadIdx.x & 31;
    if (n >= NN) return;
    int beg = g_off[n], end = g_off[n + 1];
    int col = lane * 8;

    float ed = g_ed2[n];

    float s = 0.f;
    float acc[8];
#pragma unroll
    for (int q = 0; q < 8; q++) acc[q] = 0.f;

#pragma unroll 8
    for (int i = beg; i < end; i++) {
        int sc = g_srcl[i];
        float w = __expf(lrelu(g_es2[sc] + ed));
        const float* hrow = g_h2 + (size_t)sc * DD + col;
        float4 h0 = *(const float4*)(hrow);
        float4 h1 = *(const float4*)(hrow + 4);
        s += w;
        acc[0] = fmaf(w, h0.x, acc[0]);
        acc[1] = fmaf(w, h0.y, acc[1]);
        acc[2] = fmaf(w, h0.z, acc[2]);
        acc[3] = fmaf(w, h0.w, acc[3]);
        acc[4] = fmaf(w, h1.x, acc[4]);
        acc[5] = fmaf(w, h1.y, acc[5]);
        acc[6] = fmaf(w, h1.z, acc[6]);
        acc[7] = fmaf(w, h1.w, acc[7]);
    }
    float inv = 1.f / (s + 1e-16f);
    float4 o0 = make_float4(acc[0] * inv + b2[col],     acc[1] * inv + b2[col + 1],
                            acc[2] * inv + b2[col + 2], acc[3] * inv + b2[col + 3]);
    float4 o1 = make_float4(acc[4] * inv + b2[col + 4], acc[5] * inv + b2[col + 5],
                            acc[6] * inv + b2[col + 6], acc[7] * inv + b2[col + 7]);
    float* dst = out + (size_t)n * DD + col;
    *(float4*)(dst)     = o0;
    *(float4*)(dst + 4) = o1;
}

// ---------------- launch ----------------
#define SMEM_GEMM 81920

extern "C" void kernel_launch(void* const* d_in, const int* in_sizes, int n_in,
                              void* d_out, int out_size) {
    const float* x      = (const float*)d_in[0];
    const int*   ei     = (const int*)d_in[1];
    const float* W1     = (const float*)d_in[2];
    const float* a_src1 = (const float*)d_in[3];
    const float* a_dst1 = (const float*)d_in[4];
    const float* b1     = (const float*)d_in[5];
    const float* W2     = (const float*)d_in[6];
    const float* a_src2 = (const float*)d_in[7];
    const float* a_dst2 = (const float*)d_in[8];
    const float* b2     = (const float*)d_in[9];
    float* out = (float*)d_out;

    cudaFuncSetAttribute(k_gemm_mma<1>, cudaFuncAttributeMaxDynamicSharedMemorySize, SMEM_GEMM);
    cudaFuncSetAttribute(k_gemm_mma<2>, cudaFuncAttributeMaxDynamicSharedMemorySize, SMEM_GEMM);

    dim3 gdim(2, (NN + 127) / 128);
    int warp_grid = (NN * 32 + 255) / 256;

    cudaStream_t s0 = (cudaStream_t)0;

    // fork-join: CSR build on side stream, prep+GEMM1 on main stream
    cudaStream_t s1 = 0;
    cudaEvent_t ef = 0, ej = 0;
    bool fork = (cudaStreamCreateWithFlags(&s1, cudaStreamNonBlocking) == cudaSuccess) &&
                (cudaEventCreateWithFlags(&ef, cudaEventDisableTiming) == cudaSuccess) &&
                (cudaEventCreateWithFlags(&ej, cudaEventDisableTiming) == cudaSuccess);

    cudaStream_t sc = fork ? s1 : s0;
    if (fork) {
        cudaEventRecord(ef, s0);
        cudaStreamWaitEvent(s1, ef, 0);
    }

    // CSR chain (side stream when forked)
    k_zero<<<(NN + 255) / 256, 256, 0, sc>>>();
    k_count<<<(ET + 255) / 256, 256, 0, sc>>>(ei);
    k_scan1<<<NBL, SCB, 0, sc>>>();
    k_scan2<<<1, 128, 0, sc>>>();
    k_scan3<<<NBL, SCB, 0, sc>>>();
    k_scatter<<<(ET + 255) / 256, 256, 0, sc>>>(ei);
    if (fork) cudaEventRecord(ej, s1);

    // main chain: operand prep + GEMM1 (independent of CSR)
    k_prepB<<<(256 * 128 + 256 * 256 + 255) / 256, 256, 0, s0>>>(W1, W2);
    k_prepA<<<(NN * DIN / 4 + 255) / 256, 256, 0, s0>>>(x);
    k_gemm_mma<1><<<gdim, 256, SMEM_GEMM, s0>>>(a_src1, a_dst1);

    if (fork) cudaStreamWaitEvent(s0, ej, 0);

    // layer1 aggregate (exp fused; writes split-bf16 activations)
    k_gat1<<<warp_grid, 256, 0, s0>>>(b1);

    // layer 2
    k_gemm_mma<2><<<gdim, 256, SMEM_GEMM, s0>>>(a_src2, a_dst2);
    k_gat2<<<warp_grid, 256, 0, s0>>>(b2, out);

    // cleanup only when not capturing (capture call leaks 1 stream + 2 events, once)
    cudaStreamCaptureStatus cs = cudaStreamCaptureStatusNone;
    cudaStreamIsCapturing(s0, &cs);
    if (fork && cs == cudaStreamCaptureStatusNone) {
        cudaStreamDestroy(s1);
        cudaEventDestroy(ef);
        cudaEventDestroy(ej);
    }
}

// round 11
// speedup vs baseline: 1.1925x; 1.1925x over previous
#include <cuda_runtime.h>
#include <cuda_bf16.h>
#include <cuda_fp16.h>
#include <math.h>

#define NN 50000
#define NE 500000
#define ET (NE + NN)   /* edges + self loops = 550000 */
#define DIN 128
#define DD 256
#define HH 8
#define CC 32

// ---------------- scratch (static device globals; no allocation) ----------------
__device__ __half g_h1[(size_t)NN * DD];  // layer1 GEMM out, fp16 (gather table)
__device__ float  g_act[(size_t)NN * DD]; // elu(gat1 out)    [N,256] fp32
__device__ __half g_h2[(size_t)NN * DD];  // layer2 GEMM out, fp16 (gather table)
__device__ float g_es1[NN * HH];
__device__ float g_ed1[NN * HH];
__device__ float g_es2[NN];
__device__ float g_ed2[NN];
__device__ int   g_cnt[NN];
__device__ int   g_off[NN + 1];
__device__ int   g_cur[NN];
__device__ int   g_srcl[ET];
#define SCB 512
#define NBL ((NN + SCB - 1) / SCB)   /* 98 */
__device__ int   g_bsum[NBL];
// transposed + bf16-split weights: Bt[n][k] = W[k][n]
__device__ __nv_bfloat16 g_bt1h[256 * 128];
__device__ __nv_bfloat16 g_bt1l[256 * 128];
__device__ __nv_bfloat16 g_bt2h[256 * 256];
__device__ __nv_bfloat16 g_bt2l[256 * 256];

// ---------------- helpers ----------------
__device__ __forceinline__ void cvt2(float a, float b, unsigned& hi, unsigned& lo) {
    __nv_bfloat16 ah = __float2bfloat16_rn(a), bh = __float2bfloat16_rn(b);
    float al = a - __bfloat162float(ah), bl = b - __bfloat162float(bh);
    __nv_bfloat16 alh = __float2bfloat16_rn(al), blh = __float2bfloat16_rn(bl);
    unsigned short au = *(unsigned short*)&ah, bu = *(unsigned short*)&bh;
    unsigned short alu = *(unsigned short*)&alh, blu = *(unsigned short*)&blh;
    hi = (unsigned)au | ((unsigned)bu << 16);
    lo = (unsigned)alu | ((unsigned)blu << 16);
}

__device__ __forceinline__ void mma16816(float* c, const unsigned* a, unsigned b0, unsigned b1) {
    asm volatile(
        "mma.sync.aligned.m16n8k16.row.col.f32.bf16.bf16.f32 "
        "{%0,%1,%2,%3}, {%4,%5,%6,%7}, {%8,%9}, {%0,%1,%2,%3};"
        : "+f"(c[0]), "+f"(c[1]), "+f"(c[2]), "+f"(c[3])
        : "r"(a[0]), "r"(a[1]), "r"(a[2]), "r"(a[3]), "r"(b0), "r"(b1));
}

__device__ __forceinline__ void ldsm_x4(unsigned* r, unsigned addr) {
    asm volatile("ldmatrix.sync.aligned.m8n8.x4.shared.b16 {%0,%1,%2,%3}, [%4];"
                 : "=r"(r[0]), "=r"(r[1]), "=r"(r[2]), "=r"(r[3]) : "r"(addr));
}

__device__ __forceinline__ float lrelu(float e) { return e > 0.f ? e : 0.2f * e; }

// ---------------- CSR build ----------------
__global__ void k_zero() {
    int i = blockIdx.x * blockDim.x + threadIdx.x;
    if (i < NN) { g_cnt[i] = 0; g_es2[i] = 0.f; g_ed2[i] = 0.f; }
}

__global__ void k_count(const int* __restrict__ ei) {
    int t = blockIdx.x * blockDim.x + threadIdx.x;
    if (t >= ET) return;
    int dst = (t < NE) ? ei[NE + t] : (t - NE);
    atomicAdd(&g_cnt[dst], 1);
}

__global__ void k_scan1() {
    __shared__ int wsum[16];
    int t = threadIdx.x;
    int i = blockIdx.x * SCB + t;
    int v = (i < NN) ? g_cnt[i] : 0;
#pragma unroll
    for (int o = 16; o; o >>= 1) v += __shfl_xor_sync(0xFFFFFFFFu, v, o);
    if ((t & 31) == 0) wsum[t >> 5] = v;
    __syncthreads();
    if (t < 16) {
        int s = wsum[t];
#pragma unroll
        for (int o = 8; o; o >>= 1) s += __shfl_xor_sync(0xFFFFu, s, o);
        if (t == 0) g_bsum[blockIdx.x] = s;
    }
}

__global__ void k_scan2() {
    __shared__ int s[128];
    int t = threadIdx.x;
    int v = (t < NBL) ? g_bsum[t] : 0;
    s[t] = v;
    __syncthreads();
#pragma unroll
    for (int d = 1; d < 128; d <<= 1) {
        int u = (t >= d) ? s[t - d] : 0;
        __syncthreads();
        s[t] += u;
        __syncthreads();
    }
    if (t < NBL) g_bsum[t] = s[t] - v;   // exclusive
    if (t == 0) g_off[NN] = ET;
}

__global__ void k_scan3() {
    __shared__ int s[SCB];
    int t = threadIdx.x;
    int i = blockIdx.x * SCB + t;
    int v = (i < NN) ? g_cnt[i] : 0;
    s[t] = v;
    __syncthreads();
#pragma unroll
    for (int d = 1; d < SCB; d <<= 1) {
        int u = (t >= d) ? s[t - d] : 0;
        __syncthreads();
        s[t] += u;
        __syncthreads();
    }
    if (i < NN) {
        int e = s[t] - v + g_bsum[blockIdx.x];
        g_off[i] = e;
        g_cur[i] = e;
    }
}

__global__ void k_scatter(const int* __restrict__ ei) {
    int t = blockIdx.x * blockDim.x + threadIdx.x;
    if (t >= ET) return;
    int src, dst;
    if (t < NE) { src = ei[t]; dst = ei[NE + t]; }
    else        { src = t - NE; dst = t - NE; }
    int pos = atomicAdd(&g_cur[dst], 1);
    g_srcl[pos] = src;
}

// ---------------- weight prep: transpose + bf16 split ----------------
__global__ void k_prepB(const float* __restrict__ W1, const float* __restrict__ W2) {
    int t = blockIdx.x * blockDim.x + threadIdx.x;
    if (t < 256 * 128) {
        int n = t >> 7, k = t & 127;
        float v = W1[k * 256 + n];
        __nv_bfloat16 h = __float2bfloat16_rn(v);
        g_bt1h[n * 128 + k] = h;
        g_bt1l[n * 128 + k] = __float2bfloat16_rn(v - __bfloat162float(h));
    }
    int t2 = t - 256 * 128;
    if (t2 >= 0 && t2 < 256 * 256) {
        int n = t2 >> 8, k = t2 & 255;
        float v = W2[k * 256 + n];
        __nv_bfloat16 h = __float2bfloat16_rn(v);
        g_bt2h[n * 256 + k] = h;
        g_bt2l[n * 256 + k] = __float2bfloat16_rn(v - __bfloat162float(h));
    }
}

// ---------------- HMMA GEMM, double-buffered, ldmatrix frags, fused attn dots -------
#define SROW 40
#define BUFSZ 40960
#define PLANE 10240

template <int L>
__global__ __launch_bounds__(256)
void k_gemm_mma(const float* __restrict__ Ain,
                const float* __restrict__ asrc, const float* __restrict__ adst) {
    constexpr int KD = (L == 1) ? 128 : 256;
    constexpr int NCH = KD / 32;
    const float* A = (L == 1) ? Ain : g_act;
    __half* Cc = (L == 1) ? g_h1 : g_h2;
    const __nv_bfloat16* Bh = (L == 1) ? g_bt1h : g_bt2h;
    const __nv_bfloat16* Bl = (L == 1) ? g_bt1l : g_bt2l;

    extern __shared__ char smem[];
    unsigned sbase = (unsigned)__cvta_generic_to_shared(smem);

    int tid = threadIdx.x, wid = tid >> 5, lane = tid & 31;
    int warpM = wid >> 1, warpN = wid & 1;       // 4 x 2 warp grid
    int row0 = blockIdx.y * 128, col0 = blockIdx.x * 128;

    int ar = tid >> 1, ahalf = tid & 1;
    int agr = row0 + ar;
    bool av = agr < NN;
    const float* arowb = A + (size_t)agr * KD + ahalf * 16;

    // ldmatrix lane geometry
    int g = lane >> 3, ri = lane & 7;
    int a_row = warpM * 32 + ((g & 1) ? 8 : 0) + ri;       // + mt*16 later
    int a_colx = (g & 2) ? 8 : 0;                          // + kt*16
    int b_row = warpN * 64 + ((g & 2) ? 8 : 0) + ri;       // + ntp*16
    int b_colx = (g & 1) ? 8 : 0;                          // + kt*16

    float acc[2][8][4];
#pragma unroll
    for (int mt = 0; mt < 2; mt++)
#pragma unroll
        for (int nt = 0; nt < 8; nt++)
#pragma unroll
            for (int q = 0; q < 4; q++) acc[mt][nt][q] = 0.f;

    float4 pa[4];
    uint4  pb[4];

    // ---- load + stage chunk 0 into buffer 0 ----
    {
        const float* p = arowb;
#pragma unroll
        for (int gg = 0; gg < 4; gg++)
            pa[gg] = av ? *(const float4*)(p + gg * 4) : make_float4(0.f, 0.f, 0.f, 0.f);
#pragma unroll
        for (int it = 0; it < 4; it++) {
            int seg = tid * 4 + it;
            int buf = seg >> 9, s = seg & 511;
            int n = s >> 2, sg = s & 3;
            const __nv_bfloat16* src = (buf ? Bl : Bh) + (size_t)(col0 + n) * KD + sg * 8;
            pb[it] = *(const uint4*)src;
        }
        uint4 hi4[2], lo4[2];
#pragma unroll
        for (int gg = 0; gg < 2; gg++) {
            float4 f0 = pa[gg * 2], f1 = pa[gg * 2 + 1];
            cvt2(f0.x, f0.y, hi4[gg].x, lo4[gg].x);
            cvt2(f0.z, f0.w, hi4[gg].y, lo4[gg].y);
            cvt2(f1.x, f1.y, hi4[gg].z, lo4[gg].z);
            cvt2(f1.z, f1.w, hi4[gg].w, lo4[gg].w);
        }
        char* dh = smem + ar * 80 + ahalf * 32;
        *(uint4*)(dh)              = hi4[0];
        *(uint4*)(dh + 16)         = hi4[1];
        *(uint4*)(dh + PLANE)      = lo4[0];
        *(uint4*)(dh + PLANE + 16) = lo4[1];
#pragma unroll
        for (int it = 0; it < 4; it++) {
            int seg = tid * 4 + it;
            int buf = seg >> 9, s = seg & 511;
            int n = s >> 2, sg = s & 3;
            *(uint4*)(smem + 20480 + buf * PLANE + n * 80 + sg * 16) = pb[it];
        }
    }
    __syncthreads();

    for (int ch = 0; ch < NCH; ch++) {
        // ---- prefetch next chunk's globals (latency covered by MMA below) ----
        if (ch + 1 < NCH) {
            const float* p = arowb + (ch + 1) * 32;
#pragma unroll
            for (int gg = 0; gg < 4; gg++)
                pa[gg] = av ? *(const float4*)(p + gg * 4) : make_float4(0.f, 0.f, 0.f, 0.f);
#pragma unroll
            for (int it = 0; it < 4; it++) {
                int seg = tid * 4 + it;
                int buf = seg >> 9, s = seg & 511;
                int n = s >> 2, sg = s & 3;
                const __nv_bfloat16* src = (buf ? Bl : Bh) + (size_t)(col0 + n) * KD + (ch + 1) * 32 + sg * 8;
                pb[it] = *(const uint4*)src;
            }
        }
        // ---- MMA on current buffer (ldmatrix fragment loads) ----
        {
            unsigned aHb = sbase + (unsigned)((ch & 1) * BUFSZ);
            unsigned aLb = aHb + PLANE;
            unsigned bHb = aHb + 20480;
            unsigned bLb = aHb + 30720;
#pragma unroll
            for (int kt = 0; kt < 2; kt++) {
                int acol = kt * 16 + a_colx;
                int bcol = kt * 16 + b_colx;
                unsigned aH[2][4], aL[2][4];
#pragma unroll
                for (int mt = 0; mt < 2; mt++) {
                    unsigned off = (unsigned)((a_row + mt * 16) * SROW + acol) * 2u;
                    ldsm_x4(aH[mt], aHb + off);
                    ldsm_x4(aL[mt], aLb + off);
                }
#pragma unroll
                for (int ntp = 0; ntp < 4; ntp++) {
                    unsigned off = (unsigned)((b_row + ntp * 16) * SROW + bcol) * 2u;
                    unsigned bH4[4], bL4[4];
                    ldsm_x4(bH4, bHb + off);
                    ldsm_x4(bL4, bLb + off);
#pragma unroll
                    for (int h = 0; h < 2; h++) {
                        int nt = ntp * 2 + h;
                        unsigned bH0 = bH4[h * 2], bH1 = bH4[h * 2 + 1];
                        unsigned bL0 = bL4[h * 2], bL1 = bL4[h * 2 + 1];
                        mma16816(acc[0][nt], aH[0], bH0, bH1);
                        mma16816(acc[1][nt], aH[1], bH0, bH1);
                        mma16816(acc[0][nt], aH[0], bL0, bL1);
                        mma16816(acc[1][nt], aH[1], bL0, bL1);
                        mma16816(acc[0][nt], aL[0], bH0, bH1);
                        mma16816(acc[1][nt], aL[1], bH0, bH1);
                    }
                }
            }
        }
        // ---- stage next chunk into the other buffer ----
        if (ch + 1 < NCH) {
            char* base = smem + ((ch + 1) & 1) * BUFSZ;
            uint4 hi4[2], lo4[2];
#pragma unroll
            for (int gg = 0; gg < 2; gg++) {
                float4 f0 = pa[gg * 2], f1 = pa[gg * 2 + 1];
                cvt2(f0.x, f0.y, hi4[gg].x, lo4[gg].x);
                cvt2(f0.z, f0.w, hi4[gg].y, lo4[gg].y);
                cvt2(f1.x, f1.y, hi4[gg].z, lo4[gg].z);
                cvt2(f1.z, f1.w, hi4[gg].w, lo4[gg].w);
            }
            char* dh = base + ar * 80 + ahalf * 32;
            *(uint4*)(dh)              = hi4[0];
            *(uint4*)(dh + 16)         = hi4[1];
            *(uint4*)(dh + PLANE)      = lo4[0];
            *(uint4*)(dh + PLANE + 16) = lo4[1];
#pragma unroll
            for (int it = 0; it < 4; it++) {
                int seg = tid * 4 + it;
                int buf = seg >> 9, s = seg & 511;
                int n = s >> 2, sg = s & 3;
                *(uint4*)(base + 20480 + buf * PLANE + n * 80 + sg * 16) = pb[it];
            }
        }
        __syncthreads();
    }

    // ---- epilogue: store C as fp16 (gather table) ----
#pragma unroll
    for (int mt = 0; mt < 2; mt++) {
        int r_lo = row0 + warpM * 32 + mt * 16 + (lane >> 2);
        int cc = col0 + warpN * 64 + (lane & 3) * 2;
#pragma unroll
        for (int nt = 0; nt < 8; nt++) {
            if (r_lo < NN)
                *(__half2*)(Cc + (size_t)r_lo * DD + cc + nt * 8) =
                    __floats2half2_rn(acc[mt][nt][0], acc[mt][nt][1]);
            if (r_lo + 8 < NN)
                *(__half2*)(Cc + (size_t)(r_lo + 8) * DD + cc + nt * 8) =
                    __floats2half2_rn(acc[mt][nt][2], acc[mt][nt][3]);
        }
    }

    // ---- fused attention coefficient dots (from fp32 accumulators) ----
    if (L == 1) {
        float pes[2][2][2], ped[2][2][2];
#pragma unroll
        for (int a0 = 0; a0 < 2; a0++)
#pragma unroll
            for (int a1 = 0; a1 < 2; a1++)
#pragma unroll
                for (int a2 = 0; a2 < 2; a2++) { pes[a0][a1][a2] = 0.f; ped[a0][a1][a2] = 0.f; }
#pragma unroll
        for (int nt = 0; nt < 8; nt++) {
            int colg = col0 + warpN * 64 + nt * 8 + (lane & 3) * 2;
            float a0s = __ldg(asrc + colg), a1s = __ldg(asrc + colg + 1);
            float a0d = __ldg(adst + colg), a1d = __ldg(adst + colg + 1);
            int hb = nt >> 2;
#pragma unroll
            for (int mt = 0; mt < 2; mt++) {
                pes[mt][0][hb] += acc[mt][nt][0] * a0s + acc[mt][nt][1] * a1s;
                pes[mt][1][hb] += acc[mt][nt][2] * a0s + acc[mt][nt][3] * a1s;
                ped[mt][0][hb] += acc[mt][nt][0] * a0d + acc[mt][nt][1] * a1d;
                ped[mt][1][hb] += acc[mt][nt][2] * a0d + acc[mt][nt][3] * a1d;
            }
        }
#pragma unroll
        for (int a0 = 0; a0 < 2; a0++)
#pragma unroll
            for (int a1 = 0; a1 < 2; a1++)
#pragma unroll
                for (int a2 = 0; a2 < 2; a2++) {
                    pes[a0][a1][a2] += __shfl_xor_sync(0xFFFFFFFFu, pes[a0][a1][a2], 1);
                    pes[a0][a1][a2] += __shfl_xor_sync(0xFFFFFFFFu, pes[a0][a1][a2], 2);
                    ped[a0][a1][a2] += __shfl_xor_sync(0xFFFFFFFFu, ped[a0][a1][a2], 1);
                    ped[a0][a1][a2] += __shfl_xor_sync(0xFFFFFFFFu, ped[a0][a1][a2], 2);
                }
        if ((lane & 3) == 0) {
#pragma unroll
            for (int mt = 0; mt < 2; mt++)
#pragma unroll
                for (int rs = 0; rs < 2; rs++) {
                    int node = row0 + warpM * 32 + mt * 16 + (lane >> 2) + rs * 8;
                    if (node < NN) {
#pragma unroll
                        for (int hb = 0; hb < 2; hb++) {
                            int head = blockIdx.x * 4 + warpN * 2 + hb;
                            g_es1[node * 8 + head] = pes[mt][rs][hb];
                            g_ed1[node * 8 + head] = ped[mt][rs][hb];
                        }
                    }
                }
        }
    } else {
        float pes[2][2], ped[2][2];
#pragma unroll
        for (int a0 = 0; a0 < 2; a0++)
#pragma unroll
            for (int a1 = 0; a1 < 2; a1++) { pes[a0][a1] = 0.f; ped[a0][a1] = 0.f; }
#pragma unroll
        for (int nt = 0; nt < 8; nt++) {
            int colg = col0 + warpN * 64 + nt * 8 + (lane & 3) * 2;
            float a0s = __ldg(asrc + colg), a1s = __ldg(asrc + colg + 1);
            float a0d = __ldg(adst + colg), a1d = __ldg(adst + colg + 1);
#pragma unroll
            for (int mt = 0; mt < 2; mt++) {
                pes[mt][0] += acc[mt][nt][0] * a0s + acc[mt][nt][1] * a1s;
                pes[mt][1] += acc[mt][nt][2] * a0s + acc[mt][nt][3] * a1s;
                ped[mt][0] += acc[mt][nt][0] * a0d + acc[mt][nt][1] * a1d;
                ped[mt][1] += acc[mt][nt][2] * a0d + acc[mt][nt][3] * a1d;
            }
        }
#pragma unroll
        for (int a0 = 0; a0 < 2; a0++)
#pragma unroll
            for (int a1 = 0; a1 < 2; a1++) {
                pes[a0][a1] += __shfl_xor_sync(0xFFFFFFFFu, pes[a0][a1], 1);
                pes[a0][a1] += __shfl_xor_sync(0xFFFFFFFFu, pes[a0][a1], 2);
                ped[a0][a1] += __shfl_xor_sync(0xFFFFFFFFu, ped[a0][a1], 1);
                ped[a0][a1] += __shfl_xor_sync(0xFFFFFFFFu, ped[a0][a1], 2);
            }
        if ((lane & 3) == 0) {
#pragma unroll
            for (int mt = 0; mt < 2; mt++)
#pragma unroll
                for (int rs = 0; rs < 2; rs++) {
                    int node = row0 + warpM * 32 + mt * 16 + (lane >> 2) + rs * 8;
                    if (node < NN) {
                        atomicAdd(&g_es2[node], pes[mt][rs]);
                        atomicAdd(&g_ed2[node], ped[mt][rs]);
                    }
                }
        }
    }
}

// ---------------- GAT layer 1: warp per dst node; lane owns 8 cols of one head -------
// fp16 gather table (half the L2 traffic); exp in-place
__global__ void k_gat1(const float* __restrict__ b1) {
    int n = (blockIdx.x * blockDim.x + threadIdx.x) >> 5;
    int lane = threadIdx.x & 31;
    if (n >= NN) return;
    int beg = g_off[n], end = g_off[n + 1];
    int col = lane * 8;           // cols [col, col+8) all in head lane>>2
    int head = lane >> 2;

    float ed_h = g_ed1[n * HH + head];

    float s = 0.f;
    float acc[8];
#pragma unroll
    for (int q = 0; q < 8; q++) acc[q] = 0.f;

#pragma unroll 8
    for (int i = beg; i < end; i++) {
        int sc = g_srcl[i];
        float w = __expf(lrelu(g_es1[sc * HH + head] + ed_h));
        uint4 hv = *(const uint4*)(g_h1 + (size_t)sc * DD + col);
        float2 f0 = __half22float2(*(__half2*)&hv.x);
        float2 f1 = __half22float2(*(__half2*)&hv.y);
        float2 f2 = __half22float2(*(__half2*)&hv.z);
        float2 f3 = __half22float2(*(__half2*)&hv.w);
        s += w;
        acc[0] = fmaf(w, f0.x, acc[0]);
        acc[1] = fmaf(w, f0.y, acc[1]);
        acc[2] = fmaf(w, f1.x, acc[2]);
        acc[3] = fmaf(w, f1.y, acc[3]);
        acc[4] = fmaf(w, f2.x, acc[4]);
        acc[5] = fmaf(w, f2.y, acc[5]);
        acc[6] = fmaf(w, f3.x, acc[6]);
        acc[7] = fmaf(w, f3.y, acc[7]);
    }
    float inv = 1.f / (s + 1e-16f);
    float res[8];
#pragma unroll
    for (int q = 0; q < 8; q++) {
        float v = acc[q] * inv + b1[col + q];
        res[q] = v > 0.f ? v : expm1f(v);  // ELU
    }
    float4 o0 = make_float4(res[0], res[1], res[2], res[3]);
    float4 o1 = make_float4(res[4], res[5], res[6], res[7]);
    float* dst = g_act + (size_t)n * DD + col;
    *(float4*)(dst)     = o0;
    *(float4*)(dst + 4) = o1;
}

// ---------------- GAT layer 2 (H=1, C=256): warp per dst node, lane owns 8 cols ------
__global__ void k_gat2(const float* __restrict__ b2, float* __restrict__ out) {
    int n = (blockIdx.x * blockDim.x + threadIdx.x) >> 5;
    int lane = threadIdx.x & 31;
    if (n >= NN) return;
    int beg = g_off[n], end = g_off[n + 1];
    int col = lane * 8;

    float ed = g_ed2[n];

    float s = 0.f;
    float acc[8];
#pragma unroll
    for (int q = 0; q < 8; q++) acc[q] = 0.f;

#pragma unroll 8
    for (int i = beg; i < end; i++) {
        int sc = g_srcl[i];
        float w = __expf(lrelu(g_es2[sc] + ed));
        uint4 hv = *(const uint4*)(g_h2 + (size_t)sc * DD + col);
        float2 f0 = __half22float2(*(__half2*)&hv.x);
        float2 f1 = __half22float2(*(__half2*)&hv.y);
        float2 f2 = __half22float2(*(__half2*)&hv.z);
        float2 f3 = __half22float2(*(__half2*)&hv.w);
        s += w;
        acc[0] = fmaf(w, f0.x, acc[0]);
        acc[1] = fmaf(w, f0.y, acc[1]);
        acc[2] = fmaf(w, f1.x, acc[2]);
        acc[3] = fmaf(w, f1.y, acc[3]);
        acc[4] = fmaf(w, f2.x, acc[4]);
        acc[5] = fmaf(w, f2.y, acc[5]);
        acc[6] = fmaf(w, f3.x, acc[6]);
        acc[7] = fmaf(w, f3.y, acc[7]);
    }
    float inv = 1.f / (s + 1e-16f);
    float4 o0 = make_float4(acc[0] * inv + b2[col],     acc[1] * inv + b2[col + 1],
                            acc[2] * inv + b2[col + 2], acc[3] * inv + b2[col + 3]);
    float4 o1 = make_float4(acc[4] * inv + b2[col + 4], acc[5] * inv + b2[col + 5],
                            acc[6] * inv + b2[col + 6], acc[7] * inv + b2[col + 7]);
    float* dst = out + (size_t)n * DD + col;
    *(float4*)(dst)     = o0;
    *(float4*)(dst + 4) = o1;
}

// ---------------- launch ----------------
#define SMEM_GEMM 81920

extern "C" void kernel_launch(void* const* d_in, const int* in_sizes, int n_in,
                              void* d_out, int out_size) {
    const float* x      = (const float*)d_in[0];
    const int*   ei     = (const int*)d_in[1];
    const float* W1     = (const float*)d_in[2];
    const float* a_src1 = (const float*)d_in[3];
    const float* a_dst1 = (const float*)d_in[4];
    const float* b1     = (const float*)d_in[5];
    const float* W2     = (const float*)d_in[6];
    const float* a_src2 = (const float*)d_in[7];
    const float* a_dst2 = (const float*)d_in[8];
    const float* b2     = (const float*)d_in[9];
    float* out = (float*)d_out;

    cudaFuncSetAttribute(k_gemm_mma<1>, cudaFuncAttributeMaxDynamicSharedMemorySize, SMEM_GEMM);
    cudaFuncSetAttribute(k_gemm_mma<2>, cudaFuncAttributeMaxDynamicSharedMemorySize, SMEM_GEMM);

    dim3 gdim(2, (NN + 127) / 128);
    int warp_grid = (NN * 32 + 255) / 256;

    cudaStream_t s0 = (cudaStream_t)0;

    // fork-join: CSR build on side stream, prepB+GEMM1 on main stream
    cudaStream_t s1 = 0;
    cudaEvent_t ef = 0, ej = 0;
    bool fork = (cudaStreamCreateWithFlags(&s1, cudaStreamNonBlocking) == cudaSuccess) &&
                (cudaEventCreateWithFlags(&ef, cudaEventDisableTiming) == cudaSuccess) &&
                (cudaEventCreateWithFlags(&ej, cudaEventDisableTiming) == cudaSuccess);

    cudaStream_t sc = fork ? s1 : s0;
    if (fork) {
        cudaEventRecord(ef, s0);
        cudaStreamWaitEvent(s1, ef, 0);
    }

    // CSR chain (side stream when forked)
    k_zero<<<(NN + 255) / 256, 256, 0, sc>>>();
    k_count<<<(ET + 255) / 256, 256, 0, sc>>>(ei);
    k_scan1<<<NBL, SCB, 0, sc>>>();
    k_scan2<<<1, 128, 0, sc>>>();
    k_scan3<<<NBL, SCB, 0, sc>>>();
    k_scatter<<<(ET + 255) / 256, 256, 0, sc>>>(ei);
    if (fork) cudaEventRecord(ej, s1);

    // main chain: weight prep + GEMM1 (independent of CSR)
    k_prepB<<<(256 * 128 + 256 * 256 + 255) / 256, 256, 0, s0>>>(W1, W2);
    k_gemm_mma<1><<<gdim, 256, SMEM_GEMM, s0>>>(x, a_src1, a_dst1);

    if (fork) cudaStreamWaitEvent(s0, ej, 0);

    // layer1 aggregate (exp fused in)
    k_gat1<<<warp_grid, 256, 0, s0>>>(b1);

    // layer 2
    k_gemm_mma<2><<<gdim, 256, SMEM_GEMM, s0>>>(nullptr, a_src2, a_dst2);
    k_gat2<<<warp_grid, 256, 0, s0>>>(b2, out);

    // cleanup only when not capturing (capture call leaks 1 stream + 2 events, once)
    cudaStreamCaptureStatus cs = cudaStreamCaptureStatusNone;
    cudaStreamIsCapturing(s0, &cs);
    if (fork && cs == cudaStreamCaptureStatusNone) {
        cudaStreamDestroy(s1);
        cudaEventDestroy(ef);
        cudaEventDestroy(ej);
    }
}

// round 12
// speedup vs baseline: 1.2369x; 1.0372x over previous
#include <cuda_runtime.h>
#include <cuda_bf16.h>
#include <cuda_fp16.h>
#include <math.h>

#define NN 50000
#define NE 500000
#define ET (NE + NN)   /* edges + self loops = 550000 */
#define DIN 128
#define DD 256
#define HH 8
#define CC 32
#define SPLIT 25088    /* node split for gat1/GEMM2 pipeline (196 tiles) */

// ---------------- scratch (static device globals; no allocation) ----------------
__device__ __half g_h1[(size_t)NN * DD];  // layer1 GEMM out, fp16 (gather table)
__device__ float  g_act[(size_t)NN * DD]; // elu(gat1 out)    [N,256] fp32
__device__ __half g_h2[(size_t)NN * DD];  // layer2 GEMM out, fp16 (gather table)
__device__ float g_es1[NN * HH];
__device__ float g_ed1[NN * HH];
__device__ float g_es2[NN];
__device__ float g_ed2[NN];
__device__ int   g_cnt[NN];
__device__ int   g_off[NN + 1];
__device__ int   g_cur[NN];
__device__ int   g_srcl[ET];
#define SCB 512
#define NBL ((NN + SCB - 1) / SCB)   /* 98 */
__device__ int   g_bsum[NBL];
// transposed + bf16-split weights: Bt[n][k] = W[k][n]
__device__ __nv_bfloat16 g_bt1h[256 * 128];
__device__ __nv_bfloat16 g_bt1l[256 * 128];
__device__ __nv_bfloat16 g_bt2h[256 * 256];
__device__ __nv_bfloat16 g_bt2l[256 * 256];

// ---------------- helpers ----------------
__device__ __forceinline__ void cvt2(float a, float b, unsigned& hi, unsigned& lo) {
    __nv_bfloat16 ah = __float2bfloat16_rn(a), bh = __float2bfloat16_rn(b);
    float al = a - __bfloat162float(ah), bl = b - __bfloat162float(bh);
    __nv_bfloat16 alh = __float2bfloat16_rn(al), blh = __float2bfloat16_rn(bl);
    unsigned short au = *(unsigned short*)&ah, bu = *(unsigned short*)&bh;
    unsigned short alu = *(unsigned short*)&alh, blu = *(unsigned short*)&blh;
    hi = (unsigned)au | ((unsigned)bu << 16);
    lo = (unsigned)alu | ((unsigned)blu << 16);
}

__device__ __forceinline__ void mma16816(float* c, const unsigned* a, unsigned b0, unsigned b1) {
    asm volatile(
        "mma.sync.aligned.m16n8k16.row.col.f32.bf16.bf16.f32 "
        "{%0,%1,%2,%3}, {%4,%5,%6,%7}, {%8,%9}, {%0,%1,%2,%3};"
        : "+f"(c[0]), "+f"(c[1]), "+f"(c[2]), "+f"(c[3])
        : "r"(a[0]), "r"(a[1]), "r"(a[2]), "r"(a[3]), "r"(b0), "r"(b1));
}

__device__ __forceinline__ void ldsm_x4(unsigned* r, unsigned addr) {
    asm volatile("ldmatrix.sync.aligned.m8n8.x4.shared.b16 {%0,%1,%2,%3}, [%4];"
                 : "=r"(r[0]), "=r"(r[1]), "=r"(r[2]), "=r"(r[3]) : "r"(addr));
}

__device__ __forceinline__ float lrelu(float e) { return e > 0.f ? e : 0.2f * e; }

// ---------------- CSR build ----------------
__global__ void k_zero() {
    int i = blockIdx.x * blockDim.x + threadIdx.x;
    if (i < NN) { g_cnt[i] = 0; g_es2[i] = 0.f; g_ed2[i] = 0.f; }
}

__global__ void k_count(const int* __restrict__ ei) {
    int t = blockIdx.x * blockDim.x + threadIdx.x;
    if (t >= ET) return;
    int dst = (t < NE) ? ei[NE + t] : (t - NE);
    atomicAdd(&g_cnt[dst], 1);
}

__global__ void k_scan1() {
    __shared__ int wsum[16];
    int t = threadIdx.x;
    int i = blockIdx.x * SCB + t;
    int v = (i < NN) ? g_cnt[i] : 0;
#pragma unroll
    for (int o = 16; o; o >>= 1) v += __shfl_xor_sync(0xFFFFFFFFu, v, o);
    if ((t & 31) == 0) wsum[t >> 5] = v;
    __syncthreads();
    if (t < 16) {
        int s = wsum[t];
#pragma unroll
        for (int o = 8; o; o >>= 1) s += __shfl_xor_sync(0xFFFFu, s, o);
        if (t == 0) g_bsum[blockIdx.x] = s;
    }
}

__global__ void k_scan2() {
    __shared__ int s[128];
    int t = threadIdx.x;
    int v = (t < NBL) ? g_bsum[t] : 0;
    s[t] = v;
    __syncthreads();
#pragma unroll
    for (int d = 1; d < 128; d <<= 1) {
        int u = (t >= d) ? s[t - d] : 0;
        __syncthreads();
        s[t] += u;
        __syncthreads();
    }
    if (t < NBL) g_bsum[t] = s[t] - v;   // exclusive
    if (t == 0) g_off[NN] = ET;
}

__global__ void k_scan3() {
    __shared__ int s[SCB];
    int t = threadIdx.x;
    int i = blockIdx.x * SCB + t;
    int v = (i < NN) ? g_cnt[i] : 0;
    s[t] = v;
    __syncthreads();
#pragma unroll
    for (int d = 1; d < SCB; d <<= 1) {
        int u = (t >= d) ? s[t - d] : 0;
        __syncthreads();
        s[t] += u;
        __syncthreads();
    }
    if (i < NN) {
        int e = s[t] - v + g_bsum[blockIdx.x];
        g_off[i] = e;
        g_cur[i] = e;
    }
}

__global__ void k_scatter(const int* __restrict__ ei) {
    int t = blockIdx.x * blockDim.x + threadIdx.x;
    if (t >= ET) return;
    int src, dst;
    if (t < NE) { src = ei[t]; dst = ei[NE + t]; }
    else        { src = t - NE; dst = t - NE; }
    int pos = atomicAdd(&g_cur[dst], 1);
    g_srcl[pos] = src;
}

// ---------------- weight prep: transpose + bf16 split ----------------
__global__ void k_prepB(const float* __restrict__ W1, const float* __restrict__ W2) {
    int t = blockIdx.x * blockDim.x + threadIdx.x;
    if (t < 256 * 128) {
        int n = t >> 7, k = t & 127;
        float v = W1[k * 256 + n];
        __nv_bfloat16 h = __float2bfloat16_rn(v);
        g_bt1h[n * 128 + k] = h;
        g_bt1l[n * 128 + k] = __float2bfloat16_rn(v - __bfloat162float(h));
    }
    int t2 = t - 256 * 128;
    if (t2 >= 0 && t2 < 256 * 256) {
        int n = t2 >> 8, k = t2 & 255;
        float v = W2[k * 256 + n];
        __nv_bfloat16 h = __float2bfloat16_rn(v);
        g_bt2h[n * 256 + k] = h;
        g_bt2l[n * 256 + k] = __float2bfloat16_rn(v - __bfloat162float(h));
    }
}

// ---------------- HMMA GEMM, double-buffered, ldmatrix frags, fused attn dots -------
#define SROW 40
#define BUFSZ 40960
#define PLANE 10240

template <int L>
__global__ __launch_bounds__(256)
void k_gemm_mma(const float* __restrict__ Ain,
                const float* __restrict__ asrc, const float* __restrict__ adst,
                int rowBase) {
    constexpr int KD = (L == 1) ? 128 : 256;
    constexpr int NCH = KD / 32;
    const float* A = (L == 1) ? Ain : g_act;
    __half* Cc = (L == 1) ? g_h1 : g_h2;
    const __nv_bfloat16* Bh = (L == 1) ? g_bt1h : g_bt2h;
    const __nv_bfloat16* Bl = (L == 1) ? g_bt1l : g_bt2l;

    extern __shared__ char smem[];
    unsigned sbase = (unsigned)__cvta_generic_to_shared(smem);

    int tid = threadIdx.x, wid = tid >> 5, lane = tid & 31;
    int warpM = wid >> 1, warpN = wid & 1;       // 4 x 2 warp grid
    int row0 = rowBase + blockIdx.y * 128, col0 = blockIdx.x * 128;

    int ar = tid >> 1, ahalf = tid & 1;
    int agr = row0 + ar;
    bool av = agr < NN;
    const float* arowb = A + (size_t)agr * KD + ahalf * 16;

    // ldmatrix lane geometry
    int g = lane >> 3, ri = lane & 7;
    int a_row = warpM * 32 + ((g & 1) ? 8 : 0) + ri;       // + mt*16 later
    int a_colx = (g & 2) ? 8 : 0;                          // + kt*16
    int b_row = warpN * 64 + ((g & 2) ? 8 : 0) + ri;       // + ntp*16
    int b_colx = (g & 1) ? 8 : 0;                          // + kt*16

    float acc[2][8][4];
#pragma unroll
    for (int mt = 0; mt < 2; mt++)
#pragma unroll
        for (int nt = 0; nt < 8; nt++)
#pragma unroll
            for (int q = 0; q < 4; q++) acc[mt][nt][q] = 0.f;

    float4 pa[4];
    uint4  pb[4];

    // ---- load + stage chunk 0 into buffer 0 ----
    {
        const float* p = arowb;
#pragma unroll
        for (int gg = 0; gg < 4; gg++)
            pa[gg] = av ? *(const float4*)(p + gg * 4) : make_float4(0.f, 0.f, 0.f, 0.f);
#pragma unroll
        for (int it = 0; it < 4; it++) {
            int seg = tid * 4 + it;
            int buf = seg >> 9, s = seg & 511;
            int n = s >> 2, sg = s & 3;
            const __nv_bfloat16* src = (buf ? Bl : Bh) + (size_t)(col0 + n) * KD + sg * 8;
            pb[it] = *(const uint4*)src;
        }
        uint4 hi4[2], lo4[2];
#pragma unroll
        for (int gg = 0; gg < 2; gg++) {
            float4 f0 = pa[gg * 2], f1 = pa[gg * 2 + 1];
            cvt2(f0.x, f0.y, hi4[gg].x, lo4[gg].x);
            cvt2(f0.z, f0.w, hi4[gg].y, lo4[gg].y);
            cvt2(f1.x, f1.y, hi4[gg].z, lo4[gg].z);
            cvt2(f1.z, f1.w, hi4[gg].w, lo4[gg].w);
        }
        char* dh = smem + ar * 80 + ahalf * 32;
        *(uint4*)(dh)              = hi4[0];
        *(uint4*)(dh + 16)         = hi4[1];
        *(uint4*)(dh + PLANE)      = lo4[0];
        *(uint4*)(dh + PLANE + 16) = lo4[1];
#pragma unroll
        for (int it = 0; it < 4; it++) {
            int seg = tid * 4 + it;
            int buf = seg >> 9, s = seg & 511;
            int n = s >> 2, sg = s & 3;
            *(uint4*)(smem + 20480 + buf * PLANE + n * 80 + sg * 16) = pb[it];
        }
    }
    __syncthreads();

    for (int ch = 0; ch < NCH; ch++) {
        // ---- prefetch next chunk's globals (latency covered by MMA below) ----
        if (ch + 1 < NCH) {
            const float* p = arowb + (ch + 1) * 32;
#pragma unroll
            for (int gg = 0; gg < 4; gg++)
                pa[gg] = av ? *(const float4*)(p + gg * 4) : make_float4(0.f, 0.f, 0.f, 0.f);
#pragma unroll
            for (int it = 0; it < 4; it++) {
                int seg = tid * 4 + it;
                int buf = seg >> 9, s = seg & 511;
                int n = s >> 2, sg = s & 3;
                const __nv_bfloat16* src = (buf ? Bl : Bh) + (size_t)(col0 + n) * KD + (ch + 1) * 32 + sg * 8;
                pb[it] = *(const uint4*)src;
            }
        }
        // ---- MMA on current buffer (ldmatrix fragment loads) ----
        {
            unsigned aHb = sbase + (unsigned)((ch & 1) * BUFSZ);
            unsigned aLb = aHb + PLANE;
            unsigned bHb = aHb + 20480;
            unsigned bLb = aHb + 30720;
#pragma unroll
            for (int kt = 0; kt < 2; kt++) {
                int acol = kt * 16 + a_colx;
                int bcol = kt * 16 + b_colx;
                unsigned aH[2][4], aL[2][4];
#pragma unroll
                for (int mt = 0; mt < 2; mt++) {
                    unsigned off = (unsigned)((a_row + mt * 16) * SROW + acol) * 2u;
                    ldsm_x4(aH[mt], aHb + off);
                    ldsm_x4(aL[mt], aLb + off);
                }
#pragma unroll
                for (int ntp = 0; ntp < 4; ntp++) {
                    unsigned off = (unsigned)((b_row + ntp * 16) * SROW + bcol) * 2u;
                    unsigned bH4[4], bL4[4];
                    ldsm_x4(bH4, bHb + off);
                    ldsm_x4(bL4, bLb + off);
#pragma unroll
                    for (int h = 0; h < 2; h++) {
                        int nt = ntp * 2 + h;
                        unsigned bH0 = bH4[h * 2], bH1 = bH4[h * 2 + 1];
                        unsigned bL0 = bL4[h * 2], bL1 = bL4[h * 2 + 1];
                        mma16816(acc[0][nt], aH[0], bH0, bH1);
                        mma16816(acc[1][nt], aH[1], bH0, bH1);
                        mma16816(acc[0][nt], aH[0], bL0, bL1);
                        mma16816(acc[1][nt], aH[1], bL0, bL1);
                        mma16816(acc[0][nt], aL[0], bH0, bH1);
                        mma16816(acc[1][nt], aL[1], bH0, bH1);
                    }
                }
            }
        }
        // ---- stage next chunk into the other buffer ----
        if (ch + 1 < NCH) {
            char* base = smem + ((ch + 1) & 1) * BUFSZ;
            uint4 hi4[2], lo4[2];
#pragma unroll
            for (int gg = 0; gg < 2; gg++) {
                float4 f0 = pa[gg * 2], f1 = pa[gg * 2 + 1];
                cvt2(f0.x, f0.y, hi4[gg].x, lo4[gg].x);
                cvt2(f0.z, f0.w, hi4[gg].y, lo4[gg].y);
                cvt2(f1.x, f1.y, hi4[gg].z, lo4[gg].z);
                cvt2(f1.z, f1.w, hi4[gg].w, lo4[gg].w);
            }
            char* dh = base + ar * 80 + ahalf * 32;
            *(uint4*)(dh)              = hi4[0];
            *(uint4*)(dh + 16)         = hi4[1];
            *(uint4*)(dh + PLANE)      = lo4[0];
            *(uint4*)(dh + PLANE + 16) = lo4[1];
#pragma unroll
            for (int it = 0; it < 4; it++) {
                int seg = tid * 4 + it;
                int buf = seg >> 9, s = seg & 511;
                int n = s >> 2, sg = s & 3;
                *(uint4*)(base + 20480 + buf * PLANE + n * 80 + sg * 16) = pb[it];
            }
        }
        __syncthreads();
    }

    // ---- epilogue: store C as fp16 (gather table) ----
#pragma unroll
    for (int mt = 0; mt < 2; mt++) {
        int r_lo = row0 + warpM * 32 + mt * 16 + (lane >> 2);
        int cc = col0 + warpN * 64 + (lane & 3) * 2;
#pragma unroll
        for (int nt = 0; nt < 8; nt++) {
            if (r_lo < NN)
                *(__half2*)(Cc + (size_t)r_lo * DD + cc + nt * 8) =
                    __floats2half2_rn(acc[mt][nt][0], acc[mt][nt][1]);
            if (r_lo + 8 < NN)
                *(__half2*)(Cc + (size_t)(r_lo + 8) * DD + cc + nt * 8) =
                    __floats2half2_rn(acc[mt][nt][2], acc[mt][nt][3]);
        }
    }

    // ---- fused attention coefficient dots (from fp32 accumulators) ----
    if (L == 1) {
        float pes[2][2][2], ped[2][2][2];
#pragma unroll
        for (int a0 = 0; a0 < 2; a0++)
#pragma unroll
            for (int a1 = 0; a1 < 2; a1++)
#pragma unroll
                for (int a2 = 0; a2 < 2; a2++) { pes[a0][a1][a2] = 0.f; ped[a0][a1][a2] = 0.f; }
#pragma unroll
        for (int nt = 0; nt < 8; nt++) {
            int colg = col0 + warpN * 64 + nt * 8 + (lane & 3) * 2;
            float a0s = __ldg(asrc + colg), a1s = __ldg(asrc + colg + 1);
            float a0d = __ldg(adst + colg), a1d = __ldg(adst + colg + 1);
            int hb = nt >> 2;
#pragma unroll
            for (int mt = 0; mt < 2; mt++) {
                pes[mt][0][hb] += acc[mt][nt][0] * a0s + acc[mt][nt][1] * a1s;
                pes[mt][1][hb] += acc[mt][nt][2] * a0s + acc[mt][nt][3] * a1s;
                ped[mt][0][hb] += acc[mt][nt][0] * a0d + acc[mt][nt][1] * a1d;
                ped[mt][1][hb] += acc[mt][nt][2] * a0d + acc[mt][nt][3] * a1d;
            }
        }
#pragma unroll
        for (int a0 = 0; a0 < 2; a0++)
#pragma unroll
            for (int a1 = 0; a1 < 2; a1++)
#pragma unroll
                for (int a2 = 0; a2 < 2; a2++) {
                    pes[a0][a1][a2] += __shfl_xor_sync(0xFFFFFFFFu, pes[a0][a1][a2], 1);
                    pes[a0][a1][a2] += __shfl_xor_sync(0xFFFFFFFFu, pes[a0][a1][a2], 2);
                    ped[a0][a1][a2] += __shfl_xor_sync(0xFFFFFFFFu, ped[a0][a1][a2], 1);
                    ped[a0][a1][a2] += __shfl_xor_sync(0xFFFFFFFFu, ped[a0][a1][a2], 2);
                }
        if ((lane & 3) == 0) {
#pragma unroll
            for (int mt = 0; mt < 2; mt++)
#pragma unroll
                for (int rs = 0; rs < 2; rs++) {
                    int node = row0 + warpM * 32 + mt * 16 + (lane >> 2) + rs * 8;
                    if (node < NN) {
#pragma unroll
                        for (int hb = 0; hb < 2; hb++) {
                            int head = blockIdx.x * 4 + warpN * 2 + hb;
                            g_es1[node * 8 + head] = pes[mt][rs][hb];
                            g_ed1[node * 8 + head] = ped[mt][rs][hb];
                        }
                    }
                }
        }
    } else {
        float pes[2][2], ped[2][2];
#pragma unroll
        for (int a0 = 0; a0 < 2; a0++)
#pragma unroll
            for (int a1 = 0; a1 < 2; a1++) { pes[a0][a1] = 0.f; ped[a0][a1] = 0.f; }
#pragma unroll
        for (int nt = 0; nt < 8; nt++) {
            int colg = col0 + warpN * 64 + nt * 8 + (lane & 3) * 2;
            float a0s = __ldg(asrc + colg), a1s = __ldg(asrc + colg + 1);
            float a0d = __ldg(adst + colg), a1d = __ldg(adst + colg + 1);
#pragma unroll
            for (int mt = 0; mt < 2; mt++) {
                pes[mt][0] += acc[mt][nt][0] * a0s + acc[mt][nt][1] * a1s;
                pes[mt][1] += acc[mt][nt][2] * a0s + acc[mt][nt][3] * a1s;
                ped[mt][0] += acc[mt][nt][0] * a0d + acc[mt][nt][1] * a1d;
                ped[mt][1] += acc[mt][nt][2] * a0d + acc[mt][nt][3] * a1d;
            }
        }
#pragma unroll
        for (int a0 = 0; a0 < 2; a0++)
#pragma unroll
            for (int a1 = 0; a1 < 2; a1++) {
                pes[a0][a1] += __shfl_xor_sync(0xFFFFFFFFu, pes[a0][a1], 1);
                pes[a0][a1] += __shfl_xor_sync(0xFFFFFFFFu, pes[a0][a1], 2);
                ped[a0][a1] += __shfl_xor_sync(0xFFFFFFFFu, ped[a0][a1], 1);
                ped[a0][a1] += __shfl_xor_sync(0xFFFFFFFFu, ped[a0][a1], 2);
            }
        if ((lane & 3) == 0) {
#pragma unroll
            for (int mt = 0; mt < 2; mt++)
#pragma unroll
                for (int rs = 0; rs < 2; rs++) {
                    int node = row0 + warpM * 32 + mt * 16 + (lane >> 2) + rs * 8;
                    if (node < NN) {
                        atomicAdd(&g_es2[node], pes[mt][rs]);
                        atomicAdd(&g_ed2[node], ped[mt][rs]);
                    }
                }
        }
    }
}

// ---------------- GAT layer 1: warp per dst node; lane owns 8 cols of one head -------
// fp16 gather table; exp in-place; node range [nodeBase, nodeEnd)
__global__ void k_gat1(const float* __restrict__ b1, int nodeBase, int nodeEnd) {
    int n = nodeBase + ((blockIdx.x * blockDim.x + threadIdx.x) >> 5);
    int lane = threadIdx.x & 31;
    if (n >= nodeEnd) return;
    int beg = g_off[n], end = g_off[n + 1];
    int col = lane * 8;           // cols [col, col+8) all in head lane>>2
    int head = lane >> 2;

    float ed_h = g_ed1[n * HH + head];

    float s = 0.f;
    float acc[8];
#pragma unroll
    for (int q = 0; q < 8; q++) acc[q] = 0.f;

#pragma unroll 8
    for (int i = beg; i < end; i++) {
        int sc = g_srcl[i];
        float w = __expf(lrelu(g_es1[sc * HH + head] + ed_h));
        uint4 hv = *(const uint4*)(g_h1 + (size_t)sc * DD + col);
        float2 f0 = __half22float2(*(__half2*)&hv.x);
        float2 f1 = __half22float2(*(__half2*)&hv.y);
        float2 f2 = __half22float2(*(__half2*)&hv.z);
        float2 f3 = __half22float2(*(__half2*)&hv.w);
        s += w;
        acc[0] = fmaf(w, f0.x, acc[0]);
        acc[1] = fmaf(w, f0.y, acc[1]);
        acc[2] = fmaf(w, f1.x, acc[2]);
        acc[3] = fmaf(w, f1.y, acc[3]);
        acc[4] = fmaf(w, f2.x, acc[4]);
        acc[5] = fmaf(w, f2.y, acc[5]);
        acc[6] = fmaf(w, f3.x, acc[6]);
        acc[7] = fmaf(w, f3.y, acc[7]);
    }
    float inv = 1.f / (s + 1e-16f);
    float res[8];
#pragma unroll
    for (int q = 0; q < 8; q++) {
        float v = acc[q] * inv + b1[col + q];
        res[q] = v > 0.f ? v : expm1f(v);  // ELU
    }
    float4 o0 = make_float4(res[0], res[1], res[2], res[3]);
    float4 o1 = make_float4(res[4], res[5], res[6], res[7]);
    float* dst = g_act + (size_t)n * DD + col;
    *(float4*)(dst)     = o0;
    *(float4*)(dst + 4) = o1;
}

// ---------------- GAT layer 2 (H=1, C=256): warp per dst node, lane owns 8 cols ------
__global__ void k_gat2(const float* __restrict__ b2, float* __restrict__ out) {
    int n = (blockIdx.x * blockDim.x + threadIdx.x) >> 5;
    int lane = threadIdx.x & 31;
    if (n >= NN) return;
    int beg = g_off[n], end = g_off[n + 1];
    int col = lane * 8;

    float ed = g_ed2[n];

    float s = 0.f;
    float acc[8];
#pragma unroll
    for (int q = 0; q < 8; q++) acc[q] = 0.f;

#pragma unroll 8
    for (int i = beg; i < end; i++) {
        int sc = g_srcl[i];
        float w = __expf(lrelu(g_es2[sc] + ed));
        uint4 hv = *(const uint4*)(g_h2 + (size_t)sc * DD + col);
        float2 f0 = __half22float2(*(__half2*)&hv.x);
        float2 f1 = __half22float2(*(__half2*)&hv.y);
        float2 f2 = __half22float2(*(__half2*)&hv.z);
        float2 f3 = __half22float2(*(__half2*)&hv.w);
        s += w;
        acc[0] = fmaf(w, f0.x, acc[0]);
        acc[1] = fmaf(w, f0.y, acc[1]);
        acc[2] = fmaf(w, f1.x, acc[2]);
        acc[3] = fmaf(w, f1.y, acc[3]);
        acc[4] = fmaf(w, f2.x, acc[4]);
        acc[5] = fmaf(w, f2.y, acc[5]);
        acc[6] = fmaf(w, f3.x, acc[6]);
        acc[7] = fmaf(w, f3.y, acc[7]);
    }
    float inv = 1.f / (s + 1e-16f);
    float4 o0 = make_float4(acc[0] * inv + b2[col],     acc[1] * inv + b2[col + 1],
                            acc[2] * inv + b2[col + 2], acc[3] * inv + b2[col + 3]);
    float4 o1 = make_float4(acc[4] * inv + b2[col + 4], acc[5] * inv + b2[col + 5],
                            acc[6] * inv + b2[col + 6], acc[7] * inv + b2[col + 7]);
    float* dst = out + (size_t)n * DD + col;
    *(float4*)(dst)     = o0;
    *(float4*)(dst + 4) = o1;
}

// ---------------- launch ----------------
#define SMEM_GEMM 81920

extern "C" void kernel_launch(void* const* d_in, const int* in_sizes, int n_in,
                              void* d_out, int out_size) {
    const float* x      = (const float*)d_in[0];
    const int*   ei     = (const int*)d_in[1];
    const float* W1     = (const float*)d_in[2];
    const float* a_src1 = (const float*)d_in[3];
    const float* a_dst1 = (const float*)d_in[4];
    const float* b1     = (const float*)d_in[5];
    const float* W2     = (const float*)d_in[6];
    const float* a_src2 = (const float*)d_in[7];
    const float* a_dst2 = (const float*)d_in[8];
    const float* b2     = (const float*)d_in[9];
    float* out = (float*)d_out;

    cudaFuncSetAttribute(k_gemm_mma<1>, cudaFuncAttributeMaxDynamicSharedMemorySize, SMEM_GEMM);
    cudaFuncSetAttribute(k_gemm_mma<2>, cudaFuncAttributeMaxDynamicSharedMemorySize, SMEM_GEMM);

    cudaStream_t s0 = (cudaStream_t)0;

    cudaStream_t s1 = 0;
    cudaEvent_t ef = 0, ej = 0, eG1 = 0, eB = 0;
    bool fork = (cudaStreamCreateWithFlags(&s1, cudaStreamNonBlocking) == cudaSuccess) &&
                (cudaEventCreateWithFlags(&ef, cudaEventDisableTiming) == cudaSuccess) &&
                (cudaEventCreateWithFlags(&ej, cudaEventDisableTiming) == cudaSuccess) &&
                (cudaEventCreateWithFlags(&eG1, cudaEventDisableTiming) == cudaSuccess) &&
                (cudaEventCreateWithFlags(&eB, cudaEventDisableTiming) == cudaSuccess);

    cudaStream_t sc = fork ? s1 : s0;
    if (fork) {
        cudaEventRecord(ef, s0);
        cudaStreamWaitEvent(s1, ef, 0);
    }

    // CSR chain (side stream when forked)
    k_zero<<<(NN + 255) / 256, 256, 0, sc>>>();
    k_count<<<(ET + 255) / 256, 256, 0, sc>>>(ei);
    k_scan1<<<NBL, SCB, 0, sc>>>();
    k_scan2<<<1, 128, 0, sc>>>();
    k_scan3<<<NBL, SCB, 0, sc>>>();
    k_scatter<<<(ET + 255) / 256, 256, 0, sc>>>(ei);
    if (fork) cudaEventRecord(ej, s1);

    // main chain: weight prep + GEMM1 (independent of CSR)
    k_prepB<<<(256 * 128 + 256 * 256 + 255) / 256, 256, 0, s0>>>(W1, W2);
    k_gemm_mma<1><<<dim3(2, (NN + 127) / 128), 256, SMEM_GEMM, s0>>>(x, a_src1, a_dst1, 0);

    if (fork) {
        cudaEventRecord(eG1, s0);
        cudaStreamWaitEvent(s0, ej, 0);   // CSR ready for gat1_A on s0
        cudaStreamWaitEvent(s1, eG1, 0);  // GEMM1 ready for gat1_B on s1

        // half A on s0: nodes [0, SPLIT)
        int gatA_blocks = (SPLIT * 32 + 255) / 256;
        k_gat1<<<gatA_blocks, 256, 0, s0>>>(b1, 0, SPLIT);
        k_gemm_mma<2><<<dim3(2, SPLIT / 128), 256, SMEM_GEMM, s0>>>(nullptr, a_src2, a_dst2, 0);

        // half B on s1: nodes [SPLIT, NN)
        int nB = NN - SPLIT;
        int gatB_blocks = (nB * 32 + 255) / 256;
        k_gat1<<<gatB_blocks, 256, 0, s1>>>(b1, SPLIT, NN);
        k_gemm_mma<2><<<dim3(2, (nB + 127) / 128), 256, SMEM_GEMM, s1>>>(nullptr, a_src2, a_dst2, SPLIT);
        cudaEventRecord(eB, s1);

        cudaStreamWaitEvent(s0, eB, 0);   // join both halves before gat2
    } else {
        // serial fallback
        int warp_grid = (NN * 32 + 255) / 256;
        k_gat1<<<warp_grid, 256, 0, s0>>>(b1, 0, NN);
        k_gemm_mma<2><<<dim3(2, (NN + 127) / 128), 256, SMEM_GEMM, s0>>>(nullptr, a_src2, a_dst2, 0);
    }

    int warp_grid = (NN * 32 + 255) / 256;
    k_gat2<<<warp_grid, 256, 0, s0>>>(b2, out);

    // cleanup only when not capturing (capture call leaks 1 stream + 4 events, once)
    cudaStreamCaptureStatus cs = cudaStreamCaptureStatusNone;
    cudaStreamIsCapturing(s0, &cs);
    if (fork && cs == cudaStreamCaptureStatusNone) {
        cudaStreamDestroy(s1);
        cudaEventDestroy(ef);
        cudaEventDestroy(ej);
        cudaEventDestroy(eG1);
        cudaEventDestroy(eB);
    }
}